// round 6
// baseline (speedup 1.0000x reference)
#include <cuda_runtime.h>
#include <cuda_bf16.h>

// CenterLoss: loss = sum_i clamp(||pred_i - centers[target_i]||^2, 1e-12, 1e12)
//             + batch*(num_classes-1)*1e-12
//
// dist >= 0 always and ~O(2*FEAT_DIM) for N(0,1) data; the clamp can only
// change the total by < 1e-12 per row (total ~3e7), so we sum unclamped.
//
// Working set (64 MB pred + 40 MB centers = 104 MB) fits in the 126 MB L2:
// in the harness's graph-replay timing loop the inputs stay L2-resident, so
// all loads use default caching (NO __ldcs -- evict-first would defeat this).
//
// pred:    [16384, 1024] f32
// centers: [10000, 1024] f32
// target:  [16384] int32
// out:     [1] f32

#define BATCH 16384
#define NUM_CLASSES 10000
#define FEAT_DIM 1024
#define THREADS 256
#define WARPS_PER_CTA (THREADS / 32)
#define ROWS_PER_WARP 2
#define GRID (BATCH / (WARPS_PER_CTA * ROWS_PER_WARP))   // 1024 CTAs -> single wave

__global__ void centerloss_init_kernel(float* out) {
    // masked-out entries contribute batch*(num_classes-1)*1e-12
    out[0] = (float)((double)BATCH * (double)(NUM_CLASSES - 1) * 1e-12);
}

__global__ __launch_bounds__(THREADS, 4)   // allow up to 64 regs: keep 8 float4 in flight
void centerloss_kernel(const float* __restrict__ pred,
                       const float* __restrict__ centers,
                       const int* __restrict__ target,
                       float* __restrict__ out) {
    const int tid  = threadIdx.x;
    const int wid  = tid >> 5;
    const int lane = tid & 31;
    // Warp w handles rows [base, base+ROWS_PER_WARP)
    const int base = (blockIdx.x * WARPS_PER_CTA + wid) * ROWS_PER_WARP;

    // Prefetch both class indices up front.
    int cls[ROWS_PER_WARP];
    #pragma unroll
    for (int r = 0; r < ROWS_PER_WARP; r++)
        cls[r] = __ldg(&target[base + r]);

    float acc = 0.0f;

    #pragma unroll
    for (int r = 0; r < ROWS_PER_WARP; r++) {
        const float4* p4 = reinterpret_cast<const float4*>(pred + (size_t)(base + r) * FEAT_DIM);
        const float4* c4 = reinterpret_cast<const float4*>(centers + (size_t)cls[r] * FEAT_DIM);

        // 1024 floats / warp-row = 8 float4 per lane, processed as two
        // chunks of 4 (p,c) pairs: 8 LDG.128 issued back-to-back per chunk
        // before any consumer -> one exposed memory latency per chunk.
        #pragma unroll
        for (int h = 0; h < 2; h++) {
            float4 p[4], c[4];
            #pragma unroll
            for (int i = 0; i < 4; i++) p[i] = p4[lane + 32 * (4 * h + i)];
            #pragma unroll
            for (int i = 0; i < 4; i++) c[i] = __ldg(&c4[lane + 32 * (4 * h + i)]);

            #pragma unroll
            for (int i = 0; i < 4; i++) {
                float d0 = p[i].x - c[i].x;
                float d1 = p[i].y - c[i].y;
                float d2 = p[i].z - c[i].z;
                float d3 = p[i].w - c[i].w;
                acc = fmaf(d0, d0, acc);
                acc = fmaf(d1, d1, acc);
                acc = fmaf(d2, d2, acc);
                acc = fmaf(d3, d3, acc);
            }
        }
    }

    // Single end-of-kernel reduction: warp -> CTA -> one atomic per CTA.
    #pragma unroll
    for (int off = 16; off > 0; off >>= 1)
        acc += __shfl_xor_sync(0xFFFFFFFFu, acc, off);

    __shared__ float warp_sums[WARPS_PER_CTA];
    if (lane == 0) warp_sums[wid] = acc;
    __syncthreads();

    if (wid == 0) {
        float v = (lane < WARPS_PER_CTA) ? warp_sums[lane] : 0.0f;
        #pragma unroll
        for (int off = 4; off > 0; off >>= 1)
            v += __shfl_xor_sync(0xFFFFFFFFu, v, off);
        if (lane == 0)
            atomicAdd(out, v);
    }
}

extern "C" void kernel_launch(void* const* d_in, const int* in_sizes, int n_in,
                              void* d_out, int out_size) {
    // Identify inputs by element count (robust to metadata ordering).
    const float* pred    = nullptr;
    const float* centers = nullptr;
    const int*   target  = nullptr;
    for (int i = 0; i < n_in; i++) {
        if (in_sizes[i] == BATCH * FEAT_DIM)            pred    = (const float*)d_in[i];
        else if (in_sizes[i] == NUM_CLASSES * FEAT_DIM) centers = (const float*)d_in[i];
        else if (in_sizes[i] == BATCH)                  target  = (const int*)d_in[i];
    }
    float* out = (float*)d_out;

    centerloss_init_kernel<<<1, 1>>>(out);
    centerloss_kernel<<<GRID, THREADS>>>(pred, centers, target, out);
}